// round 14
// baseline (speedup 1.0000x reference)
#include <cuda_runtime.h>

#define BB 32
#define SS 3136
#define CC 256
#define WW 98            // SS / 32 words per channel
#define THRESH 1568      // count >= 0.5*S  -> kill pair

// scratch (no allocations allowed)
__device__ float    g_sums[BB * CC];
__device__ unsigned g_bits[BB * WW * CC];    // [b][w][c] full bit matrix
__device__ unsigned g_bitsc[BB * WW * CC];   // [b][w][k] candidate-compacted (zero-padded)
__device__ int      g_pop[BB * CC];          // per-channel live popcount
__device__ int      g_cand[BB * CC];         // candidate channel indices
__device__ int      g_ncand[BB];
__device__ int      g_kill[BB * CC];

// ---------------------------------------------------------------- k0: zero scratch
__global__ void k0_zero() {
    int t = blockIdx.x * 256 + threadIdx.x;
    if (t < BB * CC) { g_sums[t] = 0.f; g_kill[t] = 0; g_pop[t] = 0; }
}

// ---------------------------------------------------------------- k1: per-channel partial sums
__global__ void k1_sums(const float* __restrict__ x) {
    int b = blockIdx.y, chunk = blockIdx.x;
    int c = threadIdx.x;
    const float* p = x + ((size_t)b * SS + (size_t)chunk * 64) * CC + c;
    float s = 0.f;
#pragma unroll 8
    for (int r = 0; r < 64; ++r) s += p[(size_t)r * CC];
    atomicAdd(&g_sums[b * CC + c], s);
}

// ---------------------------------------------------------------- k2: pack live bits + copy x->out + popcounts
// Reversed traversal: start where k1 finished so its L2-resident tail hits.
__global__ void k2_bits(const float* __restrict__ x, float* __restrict__ out) {
    __shared__ float tile[32 * CC];
    int b = BB - 1 - (int)blockIdx.y;
    int wi = WW - 1 - (int)blockIdx.x;
    int t = threadIdx.x;
    size_t base = ((size_t)b * SS + (size_t)wi * 32) * CC;
    const float4* p4 = (const float4*)(x + base);
    float4* o4 = (float4*)(out + base);
    float4* t4 = (float4*)tile;
#pragma unroll
    for (int it = 0; it < 8; ++it) {
        int idx = it * 256 + t;              // 2048 float4 = 32 rows x 256 ch
        float4 v = __ldcs(&p4[idx]);
        t4[idx] = v;
        __stcs(&o4[idx], v);
    }
    __syncthreads();
    float m = g_sums[b * CC + t] * (1.f / SS);
    unsigned word = 0;
#pragma unroll
    for (int r = 0; r < 32; ++r)
        word |= (tile[r * CC + t] > m) ? (1u << r) : 0u;
    g_bits[((size_t)b * WW + wi) * CC + t] = word;
    atomicAdd(&g_pop[b * CC + t], __popc(word));
}

// ---------------------------------------------------------------- k2b: compact candidate channels (pop >= THRESH)
// cnt_ij <= min(pop_i, pop_j): channels with pop < THRESH can neither kill nor be killed.
__global__ void k2b_cand() {
    __shared__ int wcnt[8];
    int b = blockIdx.x, t = threadIdx.x;
    int isc = g_pop[b * CC + t] >= THRESH;
    unsigned m = __ballot_sync(0xffffffffu, isc);
    int wid = t >> 5, lane = t & 31;
    if (lane == 0) wcnt[wid] = __popc(m);
    __syncthreads();
    int base = 0;
    for (int w = 0; w < wid; ++w) base += wcnt[w];
    if (isc) g_cand[b * CC + base + __popc(m & ((1u << lane) - 1))] = t;
    if (t == 0) {
        int tot = 0;
        for (int w = 0; w < 8; ++w) tot += wcnt[w];
        g_ncand[b] = tot;
    }
}

// ---------------------------------------------------------------- k2c: gather bits into compacted columns (zero-pad)
__global__ void k2c_compact() {
    int b = blockIdx.y, w = blockIdx.x, t = threadIdx.x;
    int n = g_ncand[b];
    unsigned v = 0;
    if (t < n) v = g_bits[((size_t)b * WW + w) * CC + g_cand[b * CC + t]];
    g_bitsc[((size_t)b * WW + w) * CC + t] = v;
}

// ---------------------------------------------------------------- k3: pairwise popcount on candidates -> kill flags
__constant__ unsigned char c_ti[20] = {0,0,0,1,0,1,0,1,2,0,1,2,0,1,2,3,0,1,2,3};
__constant__ unsigned char c_tj[20] = {0,1,2,2,3,3,4,4,4,5,5,5,6,6,6,6,7,7,7,7};

__global__ __launch_bounds__(256) void k3_pairs() {
    extern __shared__ unsigned sb[];
    unsigned* sbi = sb;              // WW*64 words
    unsigned* sbj = sb + WW * 64;    // WW*32 words
    int b = blockIdx.x;
    int tile = blockIdx.y;
    int ci0 = (int)c_ti[tile] * 64;
    int cj0 = (int)c_tj[tile] * 32;
    int n = g_ncand[b];
    if (ci0 >= n || cj0 >= n) return;            // tile entirely past candidate list
    int tid = threadIdx.x;
    const unsigned* gb = g_bitsc + (size_t)b * WW * CC;

    for (int idx = tid; idx < WW * 64; idx += 256) {
        int w = idx >> 6, c = idx & 63;
        sbi[idx] = gb[w * CC + ci0 + c];
    }
    for (int idx = tid; idx < WW * 32; idx += 256) {
        int w = idx >> 5, c = idx & 31;
        sbj[idx] = gb[w * CC + cj0 + c];
    }
    __syncthreads();

    int ig = tid & 15;               // i-quad: slots ci0 + ig*4 + 0..3
    int jg = tid >> 4;               // j-pair: slots cj0 + jg*2 + 0..1
    const uint4* si4 = (const uint4*)sbi;
    const uint2* sj2 = (const uint2*)sbj;

    int cnt[8];
#pragma unroll
    for (int k = 0; k < 8; ++k) cnt[k] = 0;

#pragma unroll 2
    for (int w = 0; w < WW; ++w) {
        uint4 iv = si4[w * 16 + ig];
        uint2 jv = sj2[w * 16 + jg];
        cnt[0] += __popc(iv.x & jv.x);
        cnt[1] += __popc(iv.x & jv.y);
        cnt[2] += __popc(iv.y & jv.x);
        cnt[3] += __popc(iv.y & jv.y);
        cnt[4] += __popc(iv.z & jv.x);
        cnt[5] += __popc(iv.z & jv.y);
        cnt[6] += __popc(iv.w & jv.x);
        cnt[7] += __popc(iv.w & jv.y);
    }

#pragma unroll
    for (int a = 0; a < 4; ++a)
#pragma unroll
        for (int c = 0; c < 2; ++c) {
            int si = ci0 + ig * 4 + a;
            int sj = cj0 + jg * 2 + c;
            // padded (slot >= n) columns are all-zero -> cnt 0 -> never fires
            if (cnt[a * 2 + c] >= THRESH && si != sj) {
                int gi = g_cand[b * CC + si];
                int gj = g_cand[b * CC + sj];
                atomicOr(&g_kill[b * CC + gi], 1);
                atomicOr(&g_kill[b * CC + gj], 1);
            }
        }
}

// ---------------------------------------------------------------- k4: zero out killed channels (out already = x)
__global__ void k4_fix(float* __restrict__ out) {
    int b = blockIdx.y, chunk = blockIdx.x, t = threadIdx.x;
    if (!g_kill[b * CC + t]) return;
    float* p = out + ((size_t)b * SS + (size_t)chunk * 64) * CC + t;
#pragma unroll 8
    for (int r = 0; r < 64; ++r) p[(size_t)r * CC] = 0.f;
}

// ----------------------------------------------------------------
extern "C" void kernel_launch(void* const* d_in, const int* in_sizes, int n_in,
                              void* d_out, int out_size) {
    const float* x = (const float*)d_in[0];
    float* out = (float*)d_out;

    k0_zero<<<(BB * CC + 255) / 256, 256>>>();

    dim3 g1(49, BB);
    k1_sums<<<g1, 256>>>(x);

    dim3 g2(WW, BB);
    k2_bits<<<g2, 256>>>(x, out);

    k2b_cand<<<BB, 256>>>();

    dim3 g2c(WW, BB);
    k2c_compact<<<g2c, 256>>>();

    int smem3 = WW * (64 + 32) * (int)sizeof(unsigned);   // 37632 B
    dim3 g3(BB, 20);
    k3_pairs<<<g3, 256, smem3>>>();

    dim3 g4(49, BB);
    k4_fix<<<g4, 256>>>(out);
}

// round 15
// speedup vs baseline: 1.0203x; 1.0203x over previous
#include <cuda_runtime.h>

#define BB 32
#define SS 3136
#define CC 256
#define WW 98            // SS / 32 words per channel
#define THRESH 1568      // count >= 0.5*S  -> kill pair

// scratch (no allocations allowed)
__device__ float    g_sums[BB * CC];
__device__ unsigned g_bits[BB * WW * CC];    // [b][w][c] full bit matrix
__device__ int      g_pop[BB * CC];          // per-channel live popcount
__device__ int      g_kill[BB * CC];

// ---------------------------------------------------------------- k0: zero scratch
__global__ void k0_zero() {
    int t = blockIdx.x * 256 + threadIdx.x;
    if (t < BB * CC) { g_sums[t] = 0.f; g_kill[t] = 0; g_pop[t] = 0; }
}

// ---------------------------------------------------------------- k1: per-channel partial sums
__global__ void k1_sums(const float* __restrict__ x) {
    int b = blockIdx.y, chunk = blockIdx.x;
    int c = threadIdx.x;
    const float* p = x + ((size_t)b * SS + (size_t)chunk * 64) * CC + c;
    float s = 0.f;
#pragma unroll 8
    for (int r = 0; r < 64; ++r) s += p[(size_t)r * CC];
    atomicAdd(&g_sums[b * CC + c], s);
}

// ---------------------------------------------------------------- k2: pack live bits + copy x->out + popcounts
// Reversed traversal: start where k1 finished so its L2-resident tail hits.
__global__ void k2_bits(const float* __restrict__ x, float* __restrict__ out) {
    __shared__ float tile[32 * CC];
    int b = BB - 1 - (int)blockIdx.y;
    int wi = WW - 1 - (int)blockIdx.x;
    int t = threadIdx.x;
    size_t base = ((size_t)b * SS + (size_t)wi * 32) * CC;
    const float4* p4 = (const float4*)(x + base);
    float4* o4 = (float4*)(out + base);
    float4* t4 = (float4*)tile;
#pragma unroll
    for (int it = 0; it < 8; ++it) {
        int idx = it * 256 + t;              // 2048 float4 = 32 rows x 256 ch
        float4 v = __ldcs(&p4[idx]);
        t4[idx] = v;
        __stcs(&o4[idx], v);
    }
    __syncthreads();
    float m = g_sums[b * CC + t] * (1.f / SS);
    unsigned word = 0;
#pragma unroll
    for (int r = 0; r < 32; ++r)
        word |= (tile[r * CC + t] > m) ? (1u << r) : 0u;
    g_bits[((size_t)b * WW + wi) * CC + t] = word;
    atomicAdd(&g_pop[b * CC + t], __popc(word));
}

// ---------------------------------------------------------------- k3: candidate compaction (in-block) + pairwise popcount
// cnt_ij <= min(pop_i, pop_j): channels with pop < THRESH can neither kill nor be killed.
// Each block recomputes the candidate list itself (1KB read + ballot scan) and
// gathers its bit columns from g_bits via the indices -> no k2b/k2c kernels.
__constant__ unsigned char c_ti[20] = {0,0,0,1,0,1,0,1,2,0,1,2,0,1,2,3,0,1,2,3};
__constant__ unsigned char c_tj[20] = {0,1,2,2,3,3,4,4,4,5,5,5,6,6,6,6,7,7,7,7};

__global__ __launch_bounds__(256) void k3_pairs() {
    extern __shared__ unsigned sb[];
    unsigned* sbi = sb;              // WW*64 words
    unsigned* sbj = sb + WW * 64;    // WW*32 words
    __shared__ int scand[CC];
    __shared__ int swcnt[8];
    __shared__ int sn;

    int b = blockIdx.x;
    int tile = blockIdx.y;
    int ci0 = (int)c_ti[tile] * 64;
    int cj0 = (int)c_tj[tile] * 32;
    int tid = threadIdx.x;

    // ---- in-block candidate compaction (identical result to old k2b) ----
    {
        int isc = g_pop[b * CC + tid] >= THRESH;
        unsigned m = __ballot_sync(0xffffffffu, isc);
        int wid = tid >> 5, lane = tid & 31;
        if (lane == 0) swcnt[wid] = __popc(m);
        __syncthreads();
        int base = 0;
        for (int w = 0; w < wid; ++w) base += swcnt[w];
        if (isc) scand[base + __popc(m & ((1u << lane) - 1))] = tid;
        if (tid == 0) {
            int tot = 0;
            for (int w = 0; w < 8; ++w) tot += swcnt[w];
            sn = tot;
        }
        __syncthreads();
    }
    int n = sn;
    if (ci0 >= n || cj0 >= n) return;            // tile entirely past candidate list

    const unsigned* gb = g_bits + (size_t)b * WW * CC;

    // gather candidate columns (zero-pad slots >= n)
    for (int idx = tid; idx < WW * 64; idx += 256) {
        int w = idx >> 6, c = idx & 63;
        int slot = ci0 + c;
        sbi[idx] = (slot < n) ? gb[w * CC + scand[slot]] : 0u;
    }
    for (int idx = tid; idx < WW * 32; idx += 256) {
        int w = idx >> 5, c = idx & 31;
        int slot = cj0 + c;
        sbj[idx] = (slot < n) ? gb[w * CC + scand[slot]] : 0u;
    }
    __syncthreads();

    int ig = tid & 15;               // i-quad: slots ci0 + ig*4 + 0..3
    int jg = tid >> 4;               // j-pair: slots cj0 + jg*2 + 0..1
    const uint4* si4 = (const uint4*)sbi;
    const uint2* sj2 = (const uint2*)sbj;

    int cnt[8];
#pragma unroll
    for (int k = 0; k < 8; ++k) cnt[k] = 0;

#pragma unroll 2
    for (int w = 0; w < WW; ++w) {
        uint4 iv = si4[w * 16 + ig];
        uint2 jv = sj2[w * 16 + jg];
        cnt[0] += __popc(iv.x & jv.x);
        cnt[1] += __popc(iv.x & jv.y);
        cnt[2] += __popc(iv.y & jv.x);
        cnt[3] += __popc(iv.y & jv.y);
        cnt[4] += __popc(iv.z & jv.x);
        cnt[5] += __popc(iv.z & jv.y);
        cnt[6] += __popc(iv.w & jv.x);
        cnt[7] += __popc(iv.w & jv.y);
    }

#pragma unroll
    for (int a = 0; a < 4; ++a)
#pragma unroll
        for (int c = 0; c < 2; ++c) {
            int si = ci0 + ig * 4 + a;
            int sj = cj0 + jg * 2 + c;
            // padded (slot >= n) columns are all-zero -> cnt 0 -> never fires
            if (cnt[a * 2 + c] >= THRESH && si != sj) {
                int gi = scand[si];
                int gj = scand[sj];
                atomicOr(&g_kill[b * CC + gi], 1);
                atomicOr(&g_kill[b * CC + gj], 1);
            }
        }
}

// ---------------------------------------------------------------- k4: zero out killed channels (out already = x)
__global__ void k4_fix(float* __restrict__ out) {
    int b = blockIdx.y, chunk = blockIdx.x, t = threadIdx.x;
    if (!g_kill[b * CC + t]) return;
    float* p = out + ((size_t)b * SS + (size_t)chunk * 64) * CC + t;
#pragma unroll 8
    for (int r = 0; r < 64; ++r) p[(size_t)r * CC] = 0.f;
}

// ----------------------------------------------------------------
extern "C" void kernel_launch(void* const* d_in, const int* in_sizes, int n_in,
                              void* d_out, int out_size) {
    const float* x = (const float*)d_in[0];
    float* out = (float*)d_out;

    k0_zero<<<(BB * CC + 255) / 256, 256>>>();

    dim3 g1(49, BB);
    k1_sums<<<g1, 256>>>(x);

    dim3 g2(WW, BB);
    k2_bits<<<g2, 256>>>(x, out);

    int smem3 = WW * (64 + 32) * (int)sizeof(unsigned);   // 37632 B
    dim3 g3(BB, 20);
    k3_pairs<<<g3, 256, smem3>>>();

    dim3 g4(49, BB);
    k4_fix<<<g4, 256>>>(out);
}

// round 16
// speedup vs baseline: 1.0221x; 1.0018x over previous
#include <cuda_runtime.h>

#define BB 32
#define SS 3136
#define CC 256
#define WW 98            // SS / 32 words per channel
#define THRESH 1568      // count >= 0.5*S  -> kill pair

// scratch (no allocations allowed)
__device__ float    g_sums[BB * CC];
__device__ unsigned g_bits[BB * WW * CC];    // [b][w][c] full bit matrix
__device__ int      g_pop[BB * CC];          // per-channel live popcount
__device__ int      g_kill[BB * CC];

// ---------------------------------------------------------------- k0: zero scratch
__global__ void k0_zero() {
    int t = blockIdx.x * 256 + threadIdx.x;
    if (t < BB * CC) { g_sums[t] = 0.f; g_kill[t] = 0; g_pop[t] = 0; }
}

// ---------------------------------------------------------------- k1: per-channel partial sums
__global__ void k1_sums(const float* __restrict__ x) {
    int b = blockIdx.y, chunk = blockIdx.x;
    int c = threadIdx.x;
    const float* p = x + ((size_t)b * SS + (size_t)chunk * 64) * CC + c;
    float s = 0.f;
#pragma unroll 8
    for (int r = 0; r < 64; ++r) s += p[(size_t)r * CC];
    atomicAdd(&g_sums[b * CC + c], s);
}

// ---------------------------------------------------------------- k2: pack live bits + copy x->out + popcounts
// Reversed traversal: start where k1 finished so its L2-resident tail hits.
__global__ void k2_bits(const float* __restrict__ x, float* __restrict__ out) {
    __shared__ float tile[32 * CC];
    int b = BB - 1 - (int)blockIdx.y;
    int wi = WW - 1 - (int)blockIdx.x;
    int t = threadIdx.x;
    size_t base = ((size_t)b * SS + (size_t)wi * 32) * CC;
    const float4* p4 = (const float4*)(x + base);
    float4* o4 = (float4*)(out + base);
    float4* t4 = (float4*)tile;
#pragma unroll
    for (int it = 0; it < 8; ++it) {
        int idx = it * 256 + t;              // 2048 float4 = 32 rows x 256 ch
        float4 v = __ldcs(&p4[idx]);
        t4[idx] = v;
        __stcs(&o4[idx], v);
    }
    __syncthreads();
    float m = g_sums[b * CC + t] * (1.f / SS);
    unsigned word = 0;
#pragma unroll
    for (int r = 0; r < 32; ++r)
        word |= (tile[r * CC + t] > m) ? (1u << r) : 0u;
    g_bits[((size_t)b * WW + wi) * CC + t] = word;
    atomicAdd(&g_pop[b * CC + t], __popc(word));
}

// ---------------------------------------------------------------- k3: candidate compaction (in-block) + pairwise popcount
// cnt_ij <= min(pop_i, pop_j): channels with pop < THRESH can neither kill nor be killed.
// Each block recomputes the candidate list itself (1KB read + ballot scan) and
// gathers its bit columns from g_bits via the indices -> no k2b/k2c kernels.
__constant__ unsigned char c_ti[20] = {0,0,0,1,0,1,0,1,2,0,1,2,0,1,2,3,0,1,2,3};
__constant__ unsigned char c_tj[20] = {0,1,2,2,3,3,4,4,4,5,5,5,6,6,6,6,7,7,7,7};

__global__ __launch_bounds__(256) void k3_pairs() {
    extern __shared__ unsigned sb[];
    unsigned* sbi = sb;              // WW*64 words
    unsigned* sbj = sb + WW * 64;    // WW*32 words
    __shared__ int scand[CC];
    __shared__ int swcnt[8];
    __shared__ int sn;

    int b = blockIdx.x;
    int tile = blockIdx.y;
    int ci0 = (int)c_ti[tile] * 64;
    int cj0 = (int)c_tj[tile] * 32;
    int tid = threadIdx.x;

    // ---- in-block candidate compaction (identical result to old k2b) ----
    {
        int isc = g_pop[b * CC + tid] >= THRESH;
        unsigned m = __ballot_sync(0xffffffffu, isc);
        int wid = tid >> 5, lane = tid & 31;
        if (lane == 0) swcnt[wid] = __popc(m);
        __syncthreads();
        int base = 0;
        for (int w = 0; w < wid; ++w) base += swcnt[w];
        if (isc) scand[base + __popc(m & ((1u << lane) - 1))] = tid;
        if (tid == 0) {
            int tot = 0;
            for (int w = 0; w < 8; ++w) tot += swcnt[w];
            sn = tot;
        }
        __syncthreads();
    }
    int n = sn;
    if (ci0 >= n || cj0 >= n) return;            // tile entirely past candidate list

    const unsigned* gb = g_bits + (size_t)b * WW * CC;

    // gather candidate columns (zero-pad slots >= n)
    for (int idx = tid; idx < WW * 64; idx += 256) {
        int w = idx >> 6, c = idx & 63;
        int slot = ci0 + c;
        sbi[idx] = (slot < n) ? gb[w * CC + scand[slot]] : 0u;
    }
    for (int idx = tid; idx < WW * 32; idx += 256) {
        int w = idx >> 5, c = idx & 31;
        int slot = cj0 + c;
        sbj[idx] = (slot < n) ? gb[w * CC + scand[slot]] : 0u;
    }
    __syncthreads();

    int ig = tid & 15;               // i-quad: slots ci0 + ig*4 + 0..3
    int jg = tid >> 4;               // j-pair: slots cj0 + jg*2 + 0..1
    const uint4* si4 = (const uint4*)sbi;
    const uint2* sj2 = (const uint2*)sbj;

    int cnt[8];
#pragma unroll
    for (int k = 0; k < 8; ++k) cnt[k] = 0;

#pragma unroll 2
    for (int w = 0; w < WW; ++w) {
        uint4 iv = si4[w * 16 + ig];
        uint2 jv = sj2[w * 16 + jg];
        cnt[0] += __popc(iv.x & jv.x);
        cnt[1] += __popc(iv.x & jv.y);
        cnt[2] += __popc(iv.y & jv.x);
        cnt[3] += __popc(iv.y & jv.y);
        cnt[4] += __popc(iv.z & jv.x);
        cnt[5] += __popc(iv.z & jv.y);
        cnt[6] += __popc(iv.w & jv.x);
        cnt[7] += __popc(iv.w & jv.y);
    }

#pragma unroll
    for (int a = 0; a < 4; ++a)
#pragma unroll
        for (int c = 0; c < 2; ++c) {
            int si = ci0 + ig * 4 + a;
            int sj = cj0 + jg * 2 + c;
            // padded (slot >= n) columns are all-zero -> cnt 0 -> never fires
            if (cnt[a * 2 + c] >= THRESH && si != sj) {
                int gi = scand[si];
                int gj = scand[sj];
                atomicOr(&g_kill[b * CC + gi], 1);
                atomicOr(&g_kill[b * CC + gj], 1);
            }
        }
}

// ---------------------------------------------------------------- k4: zero out killed channels (out already = x)
__global__ void k4_fix(float* __restrict__ out) {
    int b = blockIdx.y, chunk = blockIdx.x, t = threadIdx.x;
    if (!g_kill[b * CC + t]) return;
    float* p = out + ((size_t)b * SS + (size_t)chunk * 64) * CC + t;
#pragma unroll 8
    for (int r = 0; r < 64; ++r) p[(size_t)r * CC] = 0.f;
}

// ----------------------------------------------------------------
extern "C" void kernel_launch(void* const* d_in, const int* in_sizes, int n_in,
                              void* d_out, int out_size) {
    const float* x = (const float*)d_in[0];
    float* out = (float*)d_out;

    k0_zero<<<(BB * CC + 255) / 256, 256>>>();

    dim3 g1(49, BB);
    k1_sums<<<g1, 256>>>(x);

    dim3 g2(WW, BB);
    k2_bits<<<g2, 256>>>(x, out);

    int smem3 = WW * (64 + 32) * (int)sizeof(unsigned);   // 37632 B
    dim3 g3(BB, 20);
    k3_pairs<<<g3, 256, smem3>>>();

    dim3 g4(49, BB);
    k4_fix<<<g4, 256>>>(out);
}